// round 12
// baseline (speedup 1.0000x reference)
#include <cuda_runtime.h>
#include <cuda_fp16.h>
#include <cstdint>

#define N_TOKENS 8192
#define D_IN 2048
#define HIDDEN 2048
#define N_EXPERTS 8
#define NK16 (D_IN / 16)     // 128 k16 blocks
#define NCH  (D_IN / 64)     // 32 k64 chunks

// ---------------- scratch (device globals; no allocation) ----------------
__device__ int   g_counts[N_EXPERTS];
__device__ int   g_tokens[N_EXPERTS * N_TOKENS];
__device__ float g_wts[N_EXPERTS * N_TOKENS];
__device__ int   g_tass[2 * N_TOKENS];   // per-token expert ids
__device__ float g_wass[2 * N_TOKENS];   // per-token weights
// A fragment layout: [e][m16(512)][k16(128)][lane(32)] x 16B
__device__ uint4 g_A[(size_t)N_EXPERTS * 512 * NK16 * 32];
// B fragment layout: [e][n16(128)][k16(128)][lane(32)] x 16B
__device__ uint4 g_B[(size_t)N_EXPERTS * 128 * NK16 * 32];

// ---------------- helpers ----------------
__device__ __forceinline__ void mma16816(float c[4], uint4 a, uint32_t b0, uint32_t b1) {
    asm volatile(
        "mma.sync.aligned.m16n8k16.row.col.f32.f16.f16.f32 "
        "{%0,%1,%2,%3},{%4,%5,%6,%7},{%8,%9},{%0,%1,%2,%3};"
        : "+f"(c[0]), "+f"(c[1]), "+f"(c[2]), "+f"(c[3])
        : "r"(a.x), "r"(a.y), "r"(a.z), "r"(a.w), "r"(b0), "r"(b1));
}
__device__ __forceinline__ uint32_t h2u(__half2 h) { return *reinterpret_cast<uint32_t*>(&h); }

#define CP16(dst_u32, src_ptr) \
    asm volatile("cp.async.ca.shared.global [%0], [%1], 16;" :: "r"(dst_u32), "l"(src_ptr))

// ---------------- kernel 0: zero routing counters ----------------
__global__ void zero_counts() {
    if (threadIdx.x < N_EXPERTS) g_counts[threadIdx.x] = 0;
}

// ---------------- prep1: gating (blocks 0..1023) + format_B (1024..5119) ----------------
__global__ void prep1_kernel(const float* __restrict__ x,
                             const float* __restrict__ Wg,
                             const float* __restrict__ bg,
                             const float* __restrict__ We) {
    __shared__ uint32_t sb[4 * 8 * 32 * 4];  // 16KB (format_B path only)
    const int bx = blockIdx.x;

    if (bx < 1024) {
        // ---- gating: one warp per token ----
        int warp = threadIdx.x >> 5;
        int lane = threadIdx.x & 31;
        int n = bx * 8 + warp;

        float acc[8];
#pragma unroll
        for (int e = 0; e < 8; e++) acc[e] = 0.f;

        const float* xr = x + (size_t)n * D_IN;
        for (int i = lane; i < D_IN; i += 32) {
            float xv = xr[i];
            float4 w0 = *reinterpret_cast<const float4*>(Wg + (size_t)i * 8);
            float4 w1 = *reinterpret_cast<const float4*>(Wg + (size_t)i * 8 + 4);
            acc[0] += xv * w0.x; acc[1] += xv * w0.y; acc[2] += xv * w0.z; acc[3] += xv * w0.w;
            acc[4] += xv * w1.x; acc[5] += xv * w1.y; acc[6] += xv * w1.z; acc[7] += xv * w1.w;
        }
#pragma unroll
        for (int off = 16; off > 0; off >>= 1)
#pragma unroll
            for (int e = 0; e < 8; e++)
                acc[e] += __shfl_down_sync(0xffffffffu, acc[e], off);

        if (lane == 0) {
            float l[8];
#pragma unroll
            for (int e = 0; e < 8; e++) l[e] = acc[e] + bg[e];
            float mx = l[0];
#pragma unroll
            for (int e = 1; e < 8; e++) mx = fmaxf(mx, l[e]);
            float p[8], s = 0.f;
#pragma unroll
            for (int e = 0; e < 8; e++) { p[e] = expf(l[e] - mx); s += p[e]; }

            int i1 = 0;
#pragma unroll
            for (int e = 1; e < 8; e++) if (l[e] > l[i1]) i1 = e;
            int i2 = (i1 == 0) ? 1 : 0;
#pragma unroll
            for (int e = 0; e < 8; e++) if (e != i1 && l[e] > l[i2]) i2 = e;

            float w1v = p[i1] / s, w2v = p[i2] / s;
            int p1 = atomicAdd(&g_counts[i1], 1);
            g_tokens[i1 * N_TOKENS + p1] = n;
            g_wts[i1 * N_TOKENS + p1] = w1v;
            int p2 = atomicAdd(&g_counts[i2], 1);
            g_tokens[i2 * N_TOKENS + p2] = n;
            g_wts[i2 * N_TOKENS + p2] = w2v;
            g_tass[2 * n] = i1; g_tass[2 * n + 1] = i2;
            g_wass[2 * n] = w1v; g_wass[2 * n + 1] = w2v;
        }
        return;
    }

    // ---- format_B: We[e][k][n] -> g_B fragment layout (swizzled staging) ----
    const int idx = bx - 1024;
    const int n0 = (idx & 31) * 64;
    const int k0 = ((idx >> 5) & 15) * 128;
    const int e = idx >> 9;
    const float* W = We + (size_t)e * D_IN * HIDDEN;
    const int t = threadIdx.x;
#pragma unroll
    for (int it = 0; it < 4; it++) {
        int lin = it * 256 + t;          // 0..1023
        int rp = lin >> 4;               // k row-pair 0..63
        int c4 = lin & 15;               // float4 along n
        float4 v0 = *reinterpret_cast<const float4*>(W + (size_t)(k0 + 2 * rp) * HIDDEN + n0 + c4 * 4);
        float4 v1 = *reinterpret_cast<const float4*>(W + (size_t)(k0 + 2 * rp + 1) * HIDDEN + n0 + c4 * 4);
        float a0[4] = {v0.x, v0.y, v0.z, v0.w};
        float a1[4] = {v1.x, v1.y, v1.z, v1.w};
        int c = rp & 3;
        int reg = (rp >> 2) & 1;
        int lk16 = rp >> 3;
#pragma unroll
        for (int j = 0; j < 4; j++) {
            int n = c4 * 4 + j;
            int ln16 = n >> 4, nn = n & 15;
            int lane = (nn & 7) * 4 + c;
            int slot = ((nn >> 3) << 1) | reg;
            uint32_t u4 = (uint32_t)((ln16 * 8 + lk16) * 32 + lane);
            uint32_t su = u4 ^ (((u4 >> 8) & 3) << 1);       // anti-conflict swizzle
            sb[(su << 2) + slot] = h2u(__floats2half2_rn(a0[j], a1[j]));
        }
    }
    __syncthreads();
    uint4* gdst = g_B + ((size_t)(e * 128 + (n0 >> 4)) * NK16 + (k0 >> 4)) * 32;
#pragma unroll
    for (int i = 0; i < 4; i++) {
        uint32_t lin = (uint32_t)(i * 256 + t);
        int ln16 = lin >> 8, lk16 = (lin >> 5) & 7, lane = lin & 31;
        uint32_t rs = lin ^ (((lin >> 8) & 3) << 1);
        gdst[((size_t)ln16 * NK16 + lk16) * 32 + lane] = reinterpret_cast<uint4*>(sb)[rs];
    }
}

// ---------------- prep2: format_A (blocks 0..4095) + init_out (4096..12287) ----------------
__global__ void prep2_kernel(const float* __restrict__ x,
                             const float* __restrict__ be,
                             float* __restrict__ out) {
    __shared__ uint32_t sa[64 * 32 * 4];  // 32KB (format_A path only)
    const int bx = blockIdx.x;
    const int t = threadIdx.x;

    if (bx >= 4096) {
        // ---- init_out: out[tok] = w1*be[e1] + w2*be[e2] ----
        int tok = bx - 4096;
        int e1 = g_tass[2 * tok], e2 = g_tass[2 * tok + 1];
        float w1 = g_wass[2 * tok], w2 = g_wass[2 * tok + 1];
        const float4* be4 = reinterpret_cast<const float4*>(be);
        float4* out4 = reinterpret_cast<float4*>(out) + (size_t)tok * 512;
#pragma unroll
        for (int i = 0; i < 2; i++) {
            int c = t + i * 256;
            float4 b1 = be4[(size_t)e1 * 512 + c];
            float4 b2 = be4[(size_t)e2 * 512 + c];
            float4 r;
            r.x = w1 * b1.x + w2 * b2.x; r.y = w1 * b1.y + w2 * b2.y;
            r.z = w1 * b1.z + w2 * b2.z; r.w = w1 * b1.w + w2 * b2.w;
            out4[c] = r;
        }
        return;
    }

    // ---- format_A: gather tokens -> g_A fragment layout (swizzled staging) ----
    const int m16 = bx >> 3, e = bx & 7;
    const int cnt = g_counts[e];
    if (m16 * 16 >= cnt) return;
    const float4* x4 = reinterpret_cast<const float4*>(x);

    for (int half = 0; half < 2; half++) {
#pragma unroll
        for (int it = 0; it < 16; it++) {
            int lin = it * 256 + t;      // 0..4095
            int row = lin >> 8;          // 0..15
            int f4l = lin & 255;
            int gr = m16 * 16 + row;
            int tok = (gr < cnt) ? g_tokens[e * N_TOKENS + gr] : -1;
            float4 v = make_float4(0.f, 0.f, 0.f, 0.f);
            if (tok >= 0) v = x4[(size_t)tok * 512 + half * 256 + f4l];
            int k16l = f4l >> 2;
            int lane0 = (row & 7) * 4 + 2 * (f4l & 1);
            int reg = ((row >> 3) & 1) + (((f4l >> 1) & 1) << 1);
            uint32_t u4a = (uint32_t)(k16l * 32 + lane0);
            uint32_t sw = (u4a >> 5) & 7;                    // = k16l & 7
            sa[(((u4a) ^ sw) << 2) + reg]     = h2u(__floats2half2_rn(v.x, v.y));
            sa[(((u4a + 1) ^ sw) << 2) + reg] = h2u(__floats2half2_rn(v.z, v.w));
        }
        __syncthreads();
        uint4* gdst = g_A + ((size_t)(e * 512 + m16) * NK16 + half * 64) * 32;
#pragma unroll
        for (int i = 0; i < 8; i++) {
            uint32_t lin = (uint32_t)(i * 256 + t);
            uint32_t rs = lin ^ ((lin >> 5) & 7);
            gdst[lin] = reinterpret_cast<uint4*>(sa)[rs];
        }
        __syncthreads();
    }
}

// ---------------- gemm: 128x128 block, 256 threads (8 warps of 64x32), 2 CTAs/SM ----
// warp grid 2(m) x 4(n); 16 warps/SM for latency hiding; regs capped at 124.
// 3 stages x (A 1024 + B 1024 uint4) = 3 x 32KB = 96KB dynamic smem
#define STAGE_U4 2048
#define STAGE_B  32768
#define SMEM_GEMM (3 * STAGE_B)

__global__ void __launch_bounds__(256, 2)
moe_gemm(float* __restrict__ out) {
    extern __shared__ uint4 sm[];

    const int e = blockIdx.z;
    const int cnt = g_counts[e];
    const int m0 = blockIdx.x * 128;
    if (m0 >= cnt) return;
    const int n0 = blockIdx.y * 128;

    const int tid = threadIdx.x, lane = tid & 31, warp = tid >> 5;
    const int wm = warp >> 2, wn = warp & 3;   // 2 x 4 warps of 64x32

    const uint4* Ab = g_A + (size_t)(e * 512 + (m0 >> 4)) * NK16 * 32;
    const uint4* Bb = g_B + (size_t)(e * 128 + (n0 >> 4)) * NK16 * 32;

    const uint32_t sbase = (uint32_t)__cvta_generic_to_shared(sm);

    // accumulators: 4 m16 x (2 n16 units x 2 n8) x 4 = 64 regs
    float c[4][2][2][4];
#pragma unroll
    for (int mt = 0; mt < 4; mt++)
#pragma unroll
        for (int h = 0; h < 2; h++)
#pragma unroll
            for (int p = 0; p < 2; p++)
#pragma unroll
                for (int i = 0; i < 4; i++) c[mt][h][p][i] = 0.f;

    // staging: 256 threads x (4 A + 4 B) cp.async per chunk.
    // unit i (=k16 local), slab = warp (m16/n16 index), lane.
#define ISSUE(stage, kc) do {                                                  \
    uint32_t sd = sbase + (stage) * STAGE_B + (warp * 32 + lane) * 16;         \
    const uint4* Asrc = Ab + ((size_t)warp * NK16 + (size_t)(kc) * 4) * 32 + lane; \
    const uint4* Bsrc = Bb + ((size_t)warp * NK16 + (size_t)(kc) * 4) * 32 + lane; \
    _Pragma("unroll")                                                          \
    for (int i = 0; i < 4; i++) CP16(sd + i * 4096, Asrc + (size_t)i * 32);    \
    _Pragma("unroll")                                                          \
    for (int i = 0; i < 4; i++) CP16(sd + 16384 + i * 4096, Bsrc + (size_t)i * 32); \
} while (0)

    ISSUE(0, 0); asm volatile("cp.async.commit_group;" ::: "memory");
    ISSUE(1, 1); asm volatile("cp.async.commit_group;" ::: "memory");

    for (int kc = 0; kc < NCH; kc++) {
        asm volatile("cp.async.wait_group 1;" ::: "memory");
        __syncthreads();
        int ks = kc + 2;
        if (ks < NCH) ISSUE(ks % 3, ks);
        asm volatile("cp.async.commit_group;" ::: "memory");

        const uint4* st = sm + (kc % 3) * STAGE_U4;
#pragma unroll
        for (int k16 = 0; k16 < 4; k16++) {
            uint4 av[4], bv[2];
#pragma unroll
            for (int mt = 0; mt < 4; mt++)
                av[mt] = st[(k16 * 8 + wm * 4 + mt) * 32 + lane];
#pragma unroll
            for (int h = 0; h < 2; h++)
                bv[h] = st[1024 + (k16 * 8 + wn * 2 + h) * 32 + lane];
#pragma unroll
            for (int mt = 0; mt < 4; mt++)
#pragma unroll
                for (int h = 0; h < 2; h++) {
                    mma16816(c[mt][h][0], av[mt], bv[h].x, bv[h].y);
                    mma16816(c[mt][h][1], av[mt], bv[h].z, bv[h].w);
                }
        }
    }

    // ---------------- epilogue: out[tok] += w * acc (bias pre-folded) ----------------
    const int r = lane >> 2, q = lane & 3;
#pragma unroll
    for (int mt = 0; mt < 4; mt++)
#pragma unroll
        for (int rh = 0; rh < 2; rh++) {
            int gr = m0 + wm * 64 + mt * 16 + r + rh * 8;
            if (gr < cnt) {
                int tok = g_tokens[e * N_TOKENS + gr];
                float w = g_wts[e * N_TOKENS + gr];
                float* orow = out + (size_t)tok * HIDDEN + n0 + wn * 32;
#pragma unroll
                for (int h = 0; h < 2; h++)
#pragma unroll
                    for (int p = 0; p < 2; p++) {
                        int col = h * 16 + p * 8 + 2 * q;
                        float v0 = w * c[mt][h][p][rh * 2 + 0];
                        float v1 = w * c[mt][h][p][rh * 2 + 1];
                        asm volatile("red.global.add.v2.f32 [%0], {%1,%2};"
                                     :: "l"(orow + col), "f"(v0), "f"(v1) : "memory");
                    }
            }
        }
}

// ---------------- launch ----------------
extern "C" void kernel_launch(void* const* d_in, const int* in_sizes, int n_in,
                              void* d_out, int out_size) {
    const float* x  = (const float*)d_in[0];
    const float* Wg = (const float*)d_in[1];
    const float* bg = (const float*)d_in[2];
    const float* We = (const float*)d_in[3];
    const float* be = (const float*)d_in[4];
    float* out = (float*)d_out;

    cudaFuncSetAttribute(moe_gemm, cudaFuncAttributeMaxDynamicSharedMemorySize, SMEM_GEMM);

    zero_counts<<<1, 32>>>();
    prep1_kernel<<<5120, 256>>>(x, Wg, bg, We);
    prep2_kernel<<<12288, 256>>>(x, be, out);
    moe_gemm<<<dim3(64, 16, 8), 256, SMEM_GEMM>>>(out);
}

// round 14
// speedup vs baseline: 1.0435x; 1.0435x over previous
#include <cuda_runtime.h>
#include <cuda_fp16.h>
#include <cstdint>

#define N_TOKENS 8192
#define D_IN 2048
#define HIDDEN 2048
#define N_EXPERTS 8
#define NK16 (D_IN / 16)     // 128 k16 blocks
#define NCH  (D_IN / 64)     // 32 k64 chunks

// ---------------- scratch (device globals; no allocation) ----------------
__device__ int   g_counts[N_EXPERTS];
__device__ int   g_tokens[N_EXPERTS * N_TOKENS];
__device__ float g_wts[N_EXPERTS * N_TOKENS];
__device__ int   g_tass[2 * N_TOKENS];   // per-token expert ids
__device__ float g_wass[2 * N_TOKENS];   // per-token weights
// A fragment layout: [e][m16(512)][k16(128)][lane(32)] x 16B
__device__ uint4 g_A[(size_t)N_EXPERTS * 512 * NK16 * 32];
// B fragment layout: [e][n16(128)][k16(128)][lane(32)] x 16B
__device__ uint4 g_B[(size_t)N_EXPERTS * 128 * NK16 * 32];

// ---------------- helpers ----------------
__device__ __forceinline__ void mma16816(float c[4], uint4 a, uint32_t b0, uint32_t b1) {
    asm volatile(
        "mma.sync.aligned.m16n8k16.row.col.f32.f16.f16.f32 "
        "{%0,%1,%2,%3},{%4,%5,%6,%7},{%8,%9},{%0,%1,%2,%3};"
        : "+f"(c[0]), "+f"(c[1]), "+f"(c[2]), "+f"(c[3])
        : "r"(a.x), "r"(a.y), "r"(a.z), "r"(a.w), "r"(b0), "r"(b1));
}
__device__ __forceinline__ uint32_t h2u(__half2 h) { return *reinterpret_cast<uint32_t*>(&h); }

#define CP16(dst_u32, src_ptr) \
    asm volatile("cp.async.ca.shared.global [%0], [%1], 16;" :: "r"(dst_u32), "l"(src_ptr))

// ---------------- kernel 0: zero routing counters ----------------
__global__ void zero_counts() {
    if (threadIdx.x < N_EXPERTS) g_counts[threadIdx.x] = 0;
}

// ---------------- prep1: gating (blocks 0..1023) + format_B (1024..5119) ----------------
__global__ void prep1_kernel(const float* __restrict__ x,
                             const float* __restrict__ Wg,
                             const float* __restrict__ bg,
                             const float* __restrict__ We) {
    __shared__ uint32_t sb[4 * 8 * 32 * 4];  // 16KB (format_B path only)
    const int bx = blockIdx.x;

    if (bx < 1024) {
        // ---- gating: one warp per token ----
        int warp = threadIdx.x >> 5;
        int lane = threadIdx.x & 31;
        int n = bx * 8 + warp;

        float acc[8];
#pragma unroll
        for (int e = 0; e < 8; e++) acc[e] = 0.f;

        const float* xr = x + (size_t)n * D_IN;
        for (int i = lane; i < D_IN; i += 32) {
            float xv = xr[i];
            float4 w0 = *reinterpret_cast<const float4*>(Wg + (size_t)i * 8);
            float4 w1 = *reinterpret_cast<const float4*>(Wg + (size_t)i * 8 + 4);
            acc[0] += xv * w0.x; acc[1] += xv * w0.y; acc[2] += xv * w0.z; acc[3] += xv * w0.w;
            acc[4] += xv * w1.x; acc[5] += xv * w1.y; acc[6] += xv * w1.z; acc[7] += xv * w1.w;
        }
#pragma unroll
        for (int off = 16; off > 0; off >>= 1)
#pragma unroll
            for (int e = 0; e < 8; e++)
                acc[e] += __shfl_down_sync(0xffffffffu, acc[e], off);

        if (lane == 0) {
            float l[8];
#pragma unroll
            for (int e = 0; e < 8; e++) l[e] = acc[e] + bg[e];
            float mx = l[0];
#pragma unroll
            for (int e = 1; e < 8; e++) mx = fmaxf(mx, l[e]);
            float p[8], s = 0.f;
#pragma unroll
            for (int e = 0; e < 8; e++) { p[e] = expf(l[e] - mx); s += p[e]; }

            int i1 = 0;
#pragma unroll
            for (int e = 1; e < 8; e++) if (l[e] > l[i1]) i1 = e;
            int i2 = (i1 == 0) ? 1 : 0;
#pragma unroll
            for (int e = 0; e < 8; e++) if (e != i1 && l[e] > l[i2]) i2 = e;

            float w1v = p[i1] / s, w2v = p[i2] / s;
            int p1 = atomicAdd(&g_counts[i1], 1);
            g_tokens[i1 * N_TOKENS + p1] = n;
            g_wts[i1 * N_TOKENS + p1] = w1v;
            int p2 = atomicAdd(&g_counts[i2], 1);
            g_tokens[i2 * N_TOKENS + p2] = n;
            g_wts[i2 * N_TOKENS + p2] = w2v;
            g_tass[2 * n] = i1; g_tass[2 * n + 1] = i2;
            g_wass[2 * n] = w1v; g_wass[2 * n + 1] = w2v;
        }
        return;
    }

    // ---- format_B: We[e][k][n] -> g_B fragment layout (swizzled staging) ----
    const int idx = bx - 1024;
    const int n0 = (idx & 31) * 64;
    const int k0 = ((idx >> 5) & 15) * 128;
    const int e = idx >> 9;
    const float* W = We + (size_t)e * D_IN * HIDDEN;
    const int t = threadIdx.x;
#pragma unroll
    for (int it = 0; it < 4; it++) {
        int lin = it * 256 + t;          // 0..1023
        int rp = lin >> 4;               // k row-pair 0..63
        int c4 = lin & 15;               // float4 along n
        float4 v0 = *reinterpret_cast<const float4*>(W + (size_t)(k0 + 2 * rp) * HIDDEN + n0 + c4 * 4);
        float4 v1 = *reinterpret_cast<const float4*>(W + (size_t)(k0 + 2 * rp + 1) * HIDDEN + n0 + c4 * 4);
        float a0[4] = {v0.x, v0.y, v0.z, v0.w};
        float a1[4] = {v1.x, v1.y, v1.z, v1.w};
        int c = rp & 3;
        int reg = (rp >> 2) & 1;
        int lk16 = rp >> 3;
#pragma unroll
        for (int j = 0; j < 4; j++) {
            int n = c4 * 4 + j;
            int ln16 = n >> 4, nn = n & 15;
            int lane = (nn & 7) * 4 + c;
            int slot = ((nn >> 3) << 1) | reg;
            uint32_t u4 = (uint32_t)((ln16 * 8 + lk16) * 32 + lane);
            uint32_t su = u4 ^ (((u4 >> 8) & 3) << 1);       // anti-conflict swizzle
            sb[(su << 2) + slot] = h2u(__floats2half2_rn(a0[j], a1[j]));
        }
    }
    __syncthreads();
    uint4* gdst = g_B + ((size_t)(e * 128 + (n0 >> 4)) * NK16 + (k0 >> 4)) * 32;
#pragma unroll
    for (int i = 0; i < 4; i++) {
        uint32_t lin = (uint32_t)(i * 256 + t);
        int ln16 = lin >> 8, lk16 = (lin >> 5) & 7, lane = lin & 31;
        uint32_t rs = lin ^ (((lin >> 8) & 3) << 1);
        gdst[((size_t)ln16 * NK16 + lk16) * 32 + lane] = reinterpret_cast<uint4*>(sb)[rs];
    }
}

// ---------------- prep2: format_A (blocks 0..4095) + init_out (4096..12287) ----------------
__global__ void prep2_kernel(const float* __restrict__ x,
                             const float* __restrict__ be,
                             float* __restrict__ out) {
    __shared__ uint32_t sa[64 * 32 * 4];  // 32KB (format_A path only)
    const int bx = blockIdx.x;
    const int t = threadIdx.x;

    if (bx >= 4096) {
        // ---- init_out: out[tok] = w1*be[e1] + w2*be[e2] ----
        int tok = bx - 4096;
        int e1 = g_tass[2 * tok], e2 = g_tass[2 * tok + 1];
        float w1 = g_wass[2 * tok], w2 = g_wass[2 * tok + 1];
        const float4* be4 = reinterpret_cast<const float4*>(be);
        float4* out4 = reinterpret_cast<float4*>(out) + (size_t)tok * 512;
#pragma unroll
        for (int i = 0; i < 2; i++) {
            int c = t + i * 256;
            float4 b1 = be4[(size_t)e1 * 512 + c];
            float4 b2 = be4[(size_t)e2 * 512 + c];
            float4 r;
            r.x = w1 * b1.x + w2 * b2.x; r.y = w1 * b1.y + w2 * b2.y;
            r.z = w1 * b1.z + w2 * b2.z; r.w = w1 * b1.w + w2 * b2.w;
            out4[c] = r;
        }
        return;
    }

    // ---- format_A: gather tokens -> g_A fragment layout (swizzled staging) ----
    const int m16 = bx >> 3, e = bx & 7;
    const int cnt = g_counts[e];
    if (m16 * 16 >= cnt) return;
    const float4* x4 = reinterpret_cast<const float4*>(x);

    for (int half = 0; half < 2; half++) {
#pragma unroll
        for (int it = 0; it < 16; it++) {
            int lin = it * 256 + t;      // 0..4095
            int row = lin >> 8;          // 0..15
            int f4l = lin & 255;
            int gr = m16 * 16 + row;
            int tok = (gr < cnt) ? g_tokens[e * N_TOKENS + gr] : -1;
            float4 v = make_float4(0.f, 0.f, 0.f, 0.f);
            if (tok >= 0) v = x4[(size_t)tok * 512 + half * 256 + f4l];
            int k16l = f4l >> 2;
            int lane0 = (row & 7) * 4 + 2 * (f4l & 1);
            int reg = ((row >> 3) & 1) + (((f4l >> 1) & 1) << 1);
            uint32_t u4a = (uint32_t)(k16l * 32 + lane0);
            uint32_t sw = (u4a >> 5) & 7;                    // = k16l & 7
            sa[(((u4a) ^ sw) << 2) + reg]     = h2u(__floats2half2_rn(v.x, v.y));
            sa[(((u4a + 1) ^ sw) << 2) + reg] = h2u(__floats2half2_rn(v.z, v.w));
        }
        __syncthreads();
        uint4* gdst = g_A + ((size_t)(e * 512 + m16) * NK16 + half * 64) * 32;
#pragma unroll
        for (int i = 0; i < 8; i++) {
            uint32_t lin = (uint32_t)(i * 256 + t);
            uint32_t rs = lin ^ ((lin >> 5) & 7);
            gdst[lin] = reinterpret_cast<uint4*>(sa)[rs];
        }
        __syncthreads();
    }
}

// ---------------- gemm: 128x128 block, 128 threads (4 warps of 64x64), 2 CTAs/SM ----
// A through 3-stage cp.async smem (48KB); B direct LDG.128 from g_B with a
// 2-deep k16 register prefetch pipeline (no STS/LDS for B at all).
#define STAGE_U4 1024
#define STAGE_B  16384
#define SMEM_GEMM (3 * STAGE_B)

__global__ void __launch_bounds__(128, 2)
moe_gemm(float* __restrict__ out) {
    extern __shared__ uint4 sm[];

    const int e = blockIdx.z;
    const int cnt = g_counts[e];
    const int m0 = blockIdx.x * 128;
    if (m0 >= cnt) return;
    const int n0 = blockIdx.y * 128;

    const int tid = threadIdx.x, lane = tid & 31, warp = tid >> 5;
    const int wm = warp >> 1, wn = warp & 1;   // 2 x 2 warps of 64x64

    const uint4* Ab = g_A + (size_t)(e * 512 + (m0 >> 4)) * NK16 * 32;
    // per-warp B base: this warp covers n16 = wn*4 + h (h=0..3)
    const uint4* Bw = g_B + ((size_t)(e * 128 + (n0 >> 4) + wn * 4)) * NK16 * 32 + lane;

    const uint32_t sbase = (uint32_t)__cvta_generic_to_shared(sm);

    float c[4][4][2][4];
#pragma unroll
    for (int mt = 0; mt < 4; mt++)
#pragma unroll
        for (int h = 0; h < 4; h++)
#pragma unroll
            for (int p = 0; p < 2; p++)
#pragma unroll
                for (int i = 0; i < 4; i++) c[mt][h][p][i] = 0.f;

    // A staging: per thread 8 cp.async (16B each) per k64 chunk.
    // smem layout [k16(4)][m16(8)][lane] : index (k16*8+m16)*32+lane
#define ISSUE_A(stage, kc) do {                                                \
    uint32_t sd = sbase + (stage) * STAGE_B + ((warp * 8) * 32 + lane) * 16;   \
    const uint4* Asrc = Ab + ((size_t)(kc) * 4 + warp) * 32 + lane;            \
    _Pragma("unroll")                                                          \
    for (int i = 0; i < 8; i++) CP16(sd + i * 512, Asrc + (size_t)i * (NK16 * 32)); \
} while (0)

    ISSUE_A(0, 0); asm volatile("cp.async.commit_group;" ::: "memory");
    ISSUE_A(1, 1); asm volatile("cp.async.commit_group;" ::: "memory");

    // B register prefetch pipeline: pb[parity][h] holds k16 = k, loaded 2 ahead
    uint4 pb[2][4];
#pragma unroll
    for (int h = 0; h < 4; h++) pb[0][h] = Bw[(size_t)h * (NK16 * 32) + 0 * 32];
#pragma unroll
    for (int h = 0; h < 4; h++) pb[1][h] = Bw[(size_t)h * (NK16 * 32) + 1 * 32];

    for (int kc = 0; kc < NCH; kc++) {
        asm volatile("cp.async.wait_group 1;" ::: "memory");
        __syncthreads();
        int ks = kc + 2;
        if (ks < NCH) ISSUE_A(ks % 3, ks);
        asm volatile("cp.async.commit_group;" ::: "memory");

        const uint4* st = sm + (kc % 3) * STAGE_U4;
#pragma unroll
        for (int k16 = 0; k16 < 4; k16++) {
            const int cur = k16 & 1;
            uint4 av[4];
#pragma unroll
            for (int mt = 0; mt < 4; mt++)
                av[mt] = st[(k16 * 8 + wm * 4 + mt) * 32 + lane];
#pragma unroll
            for (int mt = 0; mt < 4; mt++)
#pragma unroll
                for (int h = 0; h < 4; h++) {
                    mma16816(c[mt][h][0], av[mt], pb[cur][h].x, pb[cur][h].y);
                    mma16816(c[mt][h][1], av[mt], pb[cur][h].z, pb[cur][h].w);
                }
            // prefetch B for k16+2 into the buffer just consumed
            int knext = kc * 4 + k16 + 2;
            if (knext < NK16) {
#pragma unroll
                for (int h = 0; h < 4; h++)
                    pb[cur][h] = Bw[(size_t)h * (NK16 * 32) + (size_t)knext * 32];
            }
        }
    }

    // ---------------- epilogue: out[tok] += w * acc (bias pre-folded) ----------------
    const int r = lane >> 2, q = lane & 3;
#pragma unroll
    for (int mt = 0; mt < 4; mt++)
#pragma unroll
        for (int rh = 0; rh < 2; rh++) {
            int gr = m0 + wm * 64 + mt * 16 + r + rh * 8;
            if (gr < cnt) {
                int tok = g_tokens[e * N_TOKENS + gr];
                float w = g_wts[e * N_TOKENS + gr];
                float* orow = out + (size_t)tok * HIDDEN + n0 + wn * 64;
#pragma unroll
                for (int h = 0; h < 4; h++)
#pragma unroll
                    for (int p = 0; p < 2; p++) {
                        int col = h * 16 + p * 8 + 2 * q;
                        float v0 = w * c[mt][h][p][rh * 2 + 0];
                        float v1 = w * c[mt][h][p][rh * 2 + 1];
                        asm volatile("red.global.add.v2.f32 [%0], {%1,%2};"
                                     :: "l"(orow + col), "f"(v0), "f"(v1) : "memory");
                    }
            }
        }
}

// ---------------- launch ----------------
extern "C" void kernel_launch(void* const* d_in, const int* in_sizes, int n_in,
                              void* d_out, int out_size) {
    const float* x  = (const float*)d_in[0];
    const float* Wg = (const float*)d_in[1];
    const float* bg = (const float*)d_in[2];
    const float* We = (const float*)d_in[3];
    const float* be = (const float*)d_in[4];
    float* out = (float*)d_out;

    cudaFuncSetAttribute(moe_gemm, cudaFuncAttributeMaxDynamicSharedMemorySize, SMEM_GEMM);

    zero_counts<<<1, 32>>>();
    prep1_kernel<<<5120, 256>>>(x, Wg, bg, We);
    prep2_kernel<<<12288, 256>>>(x, be, out);
    moe_gemm<<<dim3(64, 16, 8), 128, SMEM_GEMM>>>(out);
}

// round 17
// speedup vs baseline: 1.1007x; 1.0549x over previous
#include <cuda_runtime.h>
#include <cuda_fp16.h>
#include <cstdint>

#define N_TOKENS 8192
#define D_IN 2048
#define HIDDEN 2048
#define N_EXPERTS 8
#define NK16 (D_IN / 16)     // 128 k16 blocks
#define NCH  (D_IN / 128)    // 16 k128 chunks

// ---------------- scratch (device globals; no allocation) ----------------
__device__ int   g_counts[N_EXPERTS];
__device__ int   g_tokens[N_EXPERTS * N_TOKENS];
__device__ float g_wts[N_EXPERTS * N_TOKENS];
__device__ int   g_tass[2 * N_TOKENS];   // per-token expert ids
__device__ float g_wass[2 * N_TOKENS];   // per-token weights
__device__ int   g_tile_off[N_EXPERTS + 1];  // prefix of per-expert m-tile counts
// A fragment layout: [e][m16(512)][k16(128)][lane(32)] x 16B
__device__ uint4 g_A[(size_t)N_EXPERTS * 512 * NK16 * 32];
// B fragment layout: [e][n16(128)][k16(128)][lane(32)] x 16B
__device__ uint4 g_B[(size_t)N_EXPERTS * 128 * NK16 * 32];

// ---------------- helpers ----------------
__device__ __forceinline__ void mma16816(float c[4], uint4 a, uint32_t b0, uint32_t b1) {
    asm volatile(
        "mma.sync.aligned.m16n8k16.row.col.f32.f16.f16.f32 "
        "{%0,%1,%2,%3},{%4,%5,%6,%7},{%8,%9},{%0,%1,%2,%3};"
        : "+f"(c[0]), "+f"(c[1]), "+f"(c[2]), "+f"(c[3])
        : "r"(a.x), "r"(a.y), "r"(a.z), "r"(a.w), "r"(b0), "r"(b1));
}
__device__ __forceinline__ uint32_t h2u(__half2 h) { return *reinterpret_cast<uint32_t*>(&h); }

#define CP16(dst_u32, src_ptr) \
    asm volatile("cp.async.ca.shared.global [%0], [%1], 16;" :: "r"(dst_u32), "l"(src_ptr))

// ---------------- kernel 0: zero routing counters ----------------
__global__ void zero_counts() {
    if (threadIdx.x < N_EXPERTS) g_counts[threadIdx.x] = 0;
}

// ---------------- tile map: prefix of per-expert m-tile counts ----------------
__global__ void tile_map_kernel() {
    if (blockIdx.x == 0 && threadIdx.x == 0) {
        int off = 0;
#pragma unroll
        for (int e = 0; e < N_EXPERTS; e++) {
            g_tile_off[e] = off;
            off += (g_counts[e] + 127) >> 7;
        }
        g_tile_off[N_EXPERTS] = off;
    }
}

// ---------------- prep1: gating (blocks 0..1023) + format_B (1024..5119) ----------------
__global__ void prep1_kernel(const float* __restrict__ x,
                             const float* __restrict__ Wg,
                             const float* __restrict__ bg,
                             const float* __restrict__ We) {
    __shared__ uint32_t sb[4 * 8 * 32 * 4];  // 16KB (format_B path only)
    const int bx = blockIdx.x;

    if (bx < 1024) {
        // ---- gating: one warp per token ----
        int warp = threadIdx.x >> 5;
        int lane = threadIdx.x & 31;
        int n = bx * 8 + warp;

        float acc[8];
#pragma unroll
        for (int e = 0; e < 8; e++) acc[e] = 0.f;

        const float* xr = x + (size_t)n * D_IN;
        for (int i = lane; i < D_IN; i += 32) {
            float xv = xr[i];
            float4 w0 = *reinterpret_cast<const float4*>(Wg + (size_t)i * 8);
            float4 w1 = *reinterpret_cast<const float4*>(Wg + (size_t)i * 8 + 4);
            acc[0] += xv * w0.x; acc[1] += xv * w0.y; acc[2] += xv * w0.z; acc[3] += xv * w0.w;
            acc[4] += xv * w1.x; acc[5] += xv * w1.y; acc[6] += xv * w1.z; acc[7] += xv * w1.w;
        }
#pragma unroll
        for (int off = 16; off > 0; off >>= 1)
#pragma unroll
            for (int e = 0; e < 8; e++)
                acc[e] += __shfl_down_sync(0xffffffffu, acc[e], off);

        if (lane == 0) {
            float l[8];
#pragma unroll
            for (int e = 0; e < 8; e++) l[e] = acc[e] + bg[e];
            float mx = l[0];
#pragma unroll
            for (int e = 1; e < 8; e++) mx = fmaxf(mx, l[e]);
            float p[8], s = 0.f;
#pragma unroll
            for (int e = 0; e < 8; e++) { p[e] = expf(l[e] - mx); s += p[e]; }

            int i1 = 0;
#pragma unroll
            for (int e = 1; e < 8; e++) if (l[e] > l[i1]) i1 = e;
            int i2 = (i1 == 0) ? 1 : 0;
#pragma unroll
            for (int e = 0; e < 8; e++) if (e != i1 && l[e] > l[i2]) i2 = e;

            float w1v = p[i1] / s, w2v = p[i2] / s;
            int p1 = atomicAdd(&g_counts[i1], 1);
            g_tokens[i1 * N_TOKENS + p1] = n;
            g_wts[i1 * N_TOKENS + p1] = w1v;
            int p2 = atomicAdd(&g_counts[i2], 1);
            g_tokens[i2 * N_TOKENS + p2] = n;
            g_wts[i2 * N_TOKENS + p2] = w2v;
            g_tass[2 * n] = i1; g_tass[2 * n + 1] = i2;
            g_wass[2 * n] = w1v; g_wass[2 * n + 1] = w2v;
        }
        return;
    }

    // ---- format_B: We[e][k][n] -> g_B fragment layout (swizzled staging) ----
    const int idx = bx - 1024;
    const int n0 = (idx & 31) * 64;
    const int k0 = ((idx >> 5) & 15) * 128;
    const int e = idx >> 9;
    const float* W = We + (size_t)e * D_IN * HIDDEN;
    const int t = threadIdx.x;
#pragma unroll
    for (int it = 0; it < 4; it++) {
        int lin = it * 256 + t;          // 0..1023
        int rp = lin >> 4;               // k row-pair 0..63
        int c4 = lin & 15;               // float4 along n
        float4 v0 = *reinterpret_cast<const float4*>(W + (size_t)(k0 + 2 * rp) * HIDDEN + n0 + c4 * 4);
        float4 v1 = *reinterpret_cast<const float4*>(W + (size_t)(k0 + 2 * rp + 1) * HIDDEN + n0 + c4 * 4);
        float a0[4] = {v0.x, v0.y, v0.z, v0.w};
        float a1[4] = {v1.x, v1.y, v1.z, v1.w};
        int c = rp & 3;
        int reg = (rp >> 2) & 1;
        int lk16 = rp >> 3;
#pragma unroll
        for (int j = 0; j < 4; j++) {
            int n = c4 * 4 + j;
            int ln16 = n >> 4, nn = n & 15;
            int lane = (nn & 7) * 4 + c;
            int slot = ((nn >> 3) << 1) | reg;
            uint32_t u4 = (uint32_t)((ln16 * 8 + lk16) * 32 + lane);
            uint32_t su = u4 ^ (((u4 >> 8) & 3) << 1);       // anti-conflict swizzle
            sb[(su << 2) + slot] = h2u(__floats2half2_rn(a0[j], a1[j]));
        }
    }
    __syncthreads();
    uint4* gdst = g_B + ((size_t)(e * 128 + (n0 >> 4)) * NK16 + (k0 >> 4)) * 32;
#pragma unroll
    for (int i = 0; i < 4; i++) {
        uint32_t lin = (uint32_t)(i * 256 + t);
        int ln16 = lin >> 8, lk16 = (lin >> 5) & 7, lane = lin & 31;
        uint32_t rs = lin ^ (((lin >> 8) & 3) << 1);
        gdst[((size_t)ln16 * NK16 + lk16) * 32 + lane] = reinterpret_cast<uint4*>(sb)[rs];
    }
}

// ---------------- prep2: format_A (blocks 0..4095) + init_out (4096..12287) ----------------
__global__ void prep2_kernel(const float* __restrict__ x,
                             const float* __restrict__ be,
                             float* __restrict__ out) {
    __shared__ uint32_t sa[64 * 32 * 4];  // 32KB (format_A path only)
    const int bx = blockIdx.x;
    const int t = threadIdx.x;

    if (bx >= 4096) {
        // ---- init_out: out[tok] = w1*be[e1] + w2*be[e2] ----
        int tok = bx - 4096;
        int e1 = g_tass[2 * tok], e2 = g_tass[2 * tok + 1];
        float w1 = g_wass[2 * tok], w2 = g_wass[2 * tok + 1];
        const float4* be4 = reinterpret_cast<const float4*>(be);
        float4* out4 = reinterpret_cast<float4*>(out) + (size_t)tok * 512;
#pragma unroll
        for (int i = 0; i < 2; i++) {
            int c = t + i * 256;
            float4 b1 = be4[(size_t)e1 * 512 + c];
            float4 b2 = be4[(size_t)e2 * 512 + c];
            float4 r;
            r.x = w1 * b1.x + w2 * b2.x; r.y = w1 * b1.y + w2 * b2.y;
            r.z = w1 * b1.z + w2 * b2.z; r.w = w1 * b1.w + w2 * b2.w;
            out4[c] = r;
        }
        return;
    }

    // ---- format_A: gather tokens -> g_A fragment layout (swizzled staging) ----
    const int m16 = bx >> 3, e = bx & 7;
    const int cnt = g_counts[e];
    if (m16 * 16 >= cnt) return;
    const float4* x4 = reinterpret_cast<const float4*>(x);

    for (int half = 0; half < 2; half++) {
#pragma unroll
        for (int it = 0; it < 16; it++) {
            int lin = it * 256 + t;      // 0..4095
            int row = lin >> 8;          // 0..15
            int f4l = lin & 255;
            int gr = m16 * 16 + row;
            int tok = (gr < cnt) ? g_tokens[e * N_TOKENS + gr] : -1;
            float4 v = make_float4(0.f, 0.f, 0.f, 0.f);
            if (tok >= 0) v = x4[(size_t)tok * 512 + half * 256 + f4l];
            int k16l = f4l >> 2;
            int lane0 = (row & 7) * 4 + 2 * (f4l & 1);
            int reg = ((row >> 3) & 1) + (((f4l >> 1) & 1) << 1);
            uint32_t u4a = (uint32_t)(k16l * 32 + lane0);
            uint32_t sw = (u4a >> 5) & 7;                    // = k16l & 7
            sa[(((u4a) ^ sw) << 2) + reg]     = h2u(__floats2half2_rn(v.x, v.y));
            sa[(((u4a + 1) ^ sw) << 2) + reg] = h2u(__floats2half2_rn(v.z, v.w));
        }
        __syncthreads();
        uint4* gdst = g_A + ((size_t)(e * 512 + m16) * NK16 + half * 64) * 32;
#pragma unroll
        for (int i = 0; i < 8; i++) {
            uint32_t lin = (uint32_t)(i * 256 + t);
            uint32_t rs = lin ^ ((lin >> 5) & 7);
            gdst[lin] = reinterpret_cast<uint4*>(sa)[rs];
        }
        __syncthreads();
    }
}

// ---------------- gemm: 128x128 tiles, compacted 1-D tile index, 4 warps of 64x64 ----
// A: 3-stage cp.async, k128 chunks (32KB stages, 96KB total, 2 CTAs/SM).
// B: direct LDG.128 from g_B, register prefetch depth 4 (covers L2 latency).
#define STAGE_U4 2048
#define STAGE_B  32768
#define SMEM_GEMM (3 * STAGE_B)

__global__ void __launch_bounds__(128, 2)
moe_gemm(float* __restrict__ out) {
    extern __shared__ uint4 sm[];

    const int bx = blockIdx.x;
    // load tile-offset table once
    int toff[N_EXPERTS + 1];
#pragma unroll
    for (int i = 0; i <= N_EXPERTS; i++) toff[i] = g_tile_off[i];
    if (bx >= toff[N_EXPERTS]) return;
    int e = 0;
#pragma unroll
    for (int i = 1; i < N_EXPERTS; i++)
        if (bx >= toff[i]) e = i;
    const int m0 = (bx - toff[e]) * 128;
    const int cnt = g_counts[e];
    const int n0 = blockIdx.y * 128;

    const int tid = threadIdx.x, lane = tid & 31, warp = tid >> 5;
    const int wm = warp >> 1, wn = warp & 1;   // 2 x 2 warps of 64x64

    const uint4* Ab = g_A + (size_t)(e * 512 + (m0 >> 4)) * NK16 * 32;
    const uint4* Bw = g_B + ((size_t)(e * 128 + (n0 >> 4) + wn * 4)) * NK16 * 32 + lane;

    const uint32_t sbase = (uint32_t)__cvta_generic_to_shared(sm);

    float c[4][4][2][4];
#pragma unroll
    for (int mt = 0; mt < 4; mt++)
#pragma unroll
        for (int h = 0; h < 4; h++)
#pragma unroll
            for (int p = 0; p < 2; p++)
#pragma unroll
                for (int i = 0; i < 4; i++) c[mt][h][p][i] = 0.f;

    // A staging: per thread 16 cp.async (16B) per k128 chunk.
    // smem [k16(8)][m16(8)][lane]; warp w covers k16 = 2w, 2w+1.
#define ISSUE_A(stage, kc) do {                                                \
    uint32_t sd = sbase + (stage) * STAGE_B;                                   \
    _Pragma("unroll")                                                          \
    for (int i = 0; i < 16; i++) {                                             \
        int k16i = warp * 2 + (i >> 3), m16i = i & 7;                          \
        CP16(sd + ((k16i * 8 + m16i) * 32 + lane) * 16,                        \
             Ab + ((size_t)m16i * NK16 + (size_t)(kc) * 8 + k16i) * 32 + lane);\
    }                                                                          \
} while (0)

    ISSUE_A(0, 0); asm volatile("cp.async.commit_group;" ::: "memory");
    ISSUE_A(1, 1); asm volatile("cp.async.commit_group;" ::: "memory");

    // B register prefetch, depth 4: slot = global_k16 & 3
    uint4 pb[4][4];
#pragma unroll
    for (int s = 0; s < 4; s++)
#pragma unroll
        for (int h = 0; h < 4; h++)
            pb[s][h] = Bw[(size_t)h * (NK16 * 32) + (size_t)s * 32];

    for (int kc = 0; kc < NCH; kc++) {
        asm volatile("cp.async.wait_group 1;" ::: "memory");
        __syncthreads();
        int ks = kc + 2;
        if (ks < NCH) ISSUE_A(ks % 3, ks);
        asm volatile("cp.async.commit_group;" ::: "memory");

        const uint4* st = sm + (kc % 3) * STAGE_U4;
#pragma unroll
        for (int k16 = 0; k16 < 8; k16++) {
            const int slot = k16 & 3;    // == (kc*8 + k16) & 3
            uint4 av[4];
#pragma unroll
            for (int mt = 0; mt < 4; mt++)
                av[mt] = st[(k16 * 8 + wm * 4 + mt) * 32 + lane];
#pragma unroll
            for (int mt = 0; mt < 4; mt++)
#pragma unroll
                for (int h = 0; h < 4; h++) {
                    mma16816(c[mt][h][0], av[mt], pb[slot][h].x, pb[slot][h].y);
                    mma16816(c[mt][h][1], av[mt], pb[slot][h].z, pb[slot][h].w);
                }
            int knext = kc * 8 + k16 + 4;
            if (knext < NK16) {
#pragma unroll
                for (int h = 0; h < 4; h++)
                    pb[slot][h] = Bw[(size_t)h * (NK16 * 32) + (size_t)knext * 32];
            }
        }
    }

    // ---------------- epilogue: out[tok] += w * acc (bias pre-folded) ----------------
    const int r = lane >> 2, q = lane & 3;
#pragma unroll
    for (int mt = 0; mt < 4; mt++)
#pragma unroll
        for (int rh = 0; rh < 2; rh++) {
            int gr = m0 + wm * 64 + mt * 16 + r + rh * 8;
            if (gr < cnt) {
                int tok = g_tokens[e * N_TOKENS + gr];
                float w = g_wts[e * N_TOKENS + gr];
                float* orow = out + (size_t)tok * HIDDEN + n0 + wn * 64;
#pragma unroll
                for (int h = 0; h < 4; h++)
#pragma unroll
                    for (int p = 0; p < 2; p++) {
                        int col = h * 16 + p * 8 + 2 * q;
                        float v0 = w * c[mt][h][p][rh * 2 + 0];
                        float v1 = w * c[mt][h][p][rh * 2 + 1];
                        asm volatile("red.global.add.v2.f32 [%0], {%1,%2};"
                                     :: "l"(orow + col), "f"(v0), "f"(v1) : "memory");
                    }
            }
        }
}

// ---------------- launch ----------------
extern "C" void kernel_launch(void* const* d_in, const int* in_sizes, int n_in,
                              void* d_out, int out_size) {
    const float* x  = (const float*)d_in[0];
    const float* Wg = (const float*)d_in[1];
    const float* bg = (const float*)d_in[2];
    const float* We = (const float*)d_in[3];
    const float* be = (const float*)d_in[4];
    float* out = (float*)d_out;

    cudaFuncSetAttribute(moe_gemm, cudaFuncAttributeMaxDynamicSharedMemorySize, SMEM_GEMM);

    zero_counts<<<1, 32>>>();
    prep1_kernel<<<5120, 256>>>(x, Wg, bg, We);
    tile_map_kernel<<<1, 32>>>();
    prep2_kernel<<<12288, 256>>>(x, be, out);
    // max m-tiles = sum(ceil(cnt_e/128)) <= 16384/128 + 8 = 136
    moe_gemm<<<dim3(136, 16, 1), 128, SMEM_GEMM>>>(out);
}